// round 11
// baseline (speedup 1.0000x reference)
#include <cuda_runtime.h>
#include <cuda_bf16.h>
#include <cstdint>
#include <math.h>

// Problem constants
#define NB 32768   // batch
#define TT 9       // time steps (T-1)
#define DD 81      // input dim
#define HH 128     // hidden
#define NG 512     // 4*HH gates
#define KW 96      // w_in K padded (81 -> 96)
#define KT 224     // weight k-cols (96 w_in + 128 h)

// Tiling: BM=64 rows/CTA, 256 threads (8 warps: 2 m-warps x 4 n-warps),
// warp tile 32m x 16n, gate processed as 2 chunks of 64 cols.
#define BM 64
#define NTH 256
#define AST 464    // A_HI row stride bytes (224 bf16 cols; 464%128=80 -> conflict-free)
#define ALST 272   // A_LO row stride bytes (h cols only, 128 bf16; 272%128=16 -> ok)
#define BSTW 208   // B w_in stride (96 bf16 = 192 used; 208%128=80 -> ok)
#define BSTH 272   // B h stride (128 bf16 = 256 used)

// SMEM map (bytes) — total 108 KB -> 2 CTAs/SM
#define SM_BIAS  0         // 2048
#define SM_A_HI  2048      // 64*464 = 29696
#define SM_A_LO  31744     // 64*272 = 17408
#define SM_BW_HI 49152     // 64*208 = 13312
#define SM_BW_LO 62464     // 13312
#define SM_BH_HI 75776     // 64*272 = 17408
#define SM_BH_LO 93184     // 17408
#define SM_TOTAL 110592

// device scratch: weights pre-split bf16 hi/lo, row-major [n][224]
__device__ __align__(16) __nv_bfloat16 g_Bh[NG * KT];
__device__ __align__(16) __nv_bfloat16 g_Bl[NG * KT];
__device__ float g_bias[NG];

// ---------------------------------------------------------------------------
// prep: split weights into bf16 hi/lo, layout [n][k=224]; fuse biases.
// ---------------------------------------------------------------------------
__global__ void prep_kernel(const float* __restrict__ W_ih,
                            const float* __restrict__ W_hh,
                            const float* __restrict__ b_ih,
                            const float* __restrict__ b_hh) {
    int idx = blockIdx.x * blockDim.x + threadIdx.x;   // 512*224 = 114688
    if (idx < NG * KT) {
        int n = idx / KT;
        int k = idx - n * KT;
        float w = 0.f;
        if (k < DD) w = W_ih[n * DD + k];
        else if (k >= KW) w = W_hh[n * HH + (k - KW)];
        __nv_bfloat16 hi = __float2bfloat16(w);
        g_Bh[idx] = hi;
        g_Bl[idx] = __float2bfloat16(w - __bfloat162float(hi));
    }
    if (idx < NG) g_bias[idx] = b_ih[idx] + b_hh[idx];
}

// ---------------------------------------------------------------------------
// attention: softmax over d of (sum_t x[b,t,d]*Wx[t]); write input_weighted.
// ---------------------------------------------------------------------------
__global__ void attn_kernel(const float* __restrict__ x,
                            const float* __restrict__ W_attn,
                            float* __restrict__ out_w) {
    int gw = (blockIdx.x * blockDim.x + threadIdx.x) >> 5;
    int lane = threadIdx.x & 31;
    if (gw >= NB) return;

    float wx[TT];
#pragma unroll
    for (int tt = 0; tt < TT; tt++) wx[tt] = W_attn[2 * HH + tt];

    const float* xb = x + (size_t)gw * TT * DD;
    float xr[3][TT];
    float pre[3];
#pragma unroll
    for (int ii = 0; ii < 3; ii++) {
        int d = lane + 32 * ii;
        float p = 0.f;
#pragma unroll
        for (int tt = 0; tt < TT; tt++) {
            float v = (d < DD) ? xb[tt * DD + d] : 0.f;
            xr[ii][tt] = v;
            p = fmaf(v, wx[tt], p);
        }
        pre[ii] = (d < DD) ? p : -3.0e38f;
    }
    float mx = fmaxf(pre[0], fmaxf(pre[1], pre[2]));
#pragma unroll
    for (int o = 16; o > 0; o >>= 1) mx = fmaxf(mx, __shfl_xor_sync(0xffffffffu, mx, o));

    float ev[3];
    float s = 0.f;
#pragma unroll
    for (int ii = 0; ii < 3; ii++) {
        int d = lane + 32 * ii;
        ev[ii] = (d < DD) ? __expf(pre[ii] - mx) : 0.f;
        s += ev[ii];
    }
#pragma unroll
    for (int o = 16; o > 0; o >>= 1) s += __shfl_xor_sync(0xffffffffu, s, o);
    float inv = 1.f / s;

    float* ob = out_w + (size_t)gw * TT * DD;
#pragma unroll
    for (int ii = 0; ii < 3; ii++) {
        int d = lane + 32 * ii;
        if (d < DD) {
            float a = ev[ii] * inv;
#pragma unroll
            for (int tt = 0; tt < TT; tt++) ob[tt * DD + d] = a * xr[ii][tt];
        }
    }
}

// ---------------------------------------------------------------------------
// helpers
// ---------------------------------------------------------------------------
__device__ __forceinline__ uint32_t smem_u32(const void* p) {
    uint32_t a;
    asm("{ .reg .u64 t; cvta.to.shared.u64 t, %1; cvt.u32.u64 %0, t; }" : "=r"(a) : "l"(p));
    return a;
}
__device__ __forceinline__ void ldsm_x4(uint32_t addr, uint32_t* r) {
    asm volatile("ldmatrix.sync.aligned.m8n8.x4.shared.b16 {%0,%1,%2,%3}, [%4];"
                 : "=r"(r[0]), "=r"(r[1]), "=r"(r[2]), "=r"(r[3]) : "r"(addr));
}
__device__ __forceinline__ void mma16816(float* d, const uint32_t* a, const uint32_t* b) {
    asm volatile(
        "mma.sync.aligned.m16n8k16.row.col.f32.bf16.bf16.f32 "
        "{%0,%1,%2,%3}, {%4,%5,%6,%7}, {%8,%9}, {%0,%1,%2,%3};"
        : "+f"(d[0]), "+f"(d[1]), "+f"(d[2]), "+f"(d[3])
        : "r"(a[0]), "r"(a[1]), "r"(a[2]), "r"(a[3]), "r"(b[0]), "r"(b[1]));
}
__device__ __forceinline__ void cp16(uint32_t dst, const void* src) {
    asm volatile("cp.async.cg.shared.global [%0], [%1], 16;"
                 :: "r"(dst), "l"(__cvta_generic_to_global(src)) : "memory");
}
__device__ __forceinline__ void cp_wait0() {
    asm volatile("cp.async.commit_group;" ::: "memory");
    asm volatile("cp.async.wait_group 0;" ::: "memory");
}
__device__ __forceinline__ float sigmoidf_(float v) {
    return __fdividef(1.f, 1.f + __expf(-v));
}
__device__ __forceinline__ float tanhf_(float v) {
    return __fdividef(2.f, 1.f + __expf(-2.f * v)) - 1.f;
}
__device__ __forceinline__ void split_pack(float v0, float v1, uint32_t& h2, uint32_t& l2) {
    __nv_bfloat16 h0 = __float2bfloat16(v0);
    __nv_bfloat16 h1 = __float2bfloat16(v1);
    float r0 = v0 - __bfloat162float(h0);
    float r1 = v1 - __bfloat162float(h1);
    __nv_bfloat162 H(h0, h1);
    __nv_bfloat162 L(__float2bfloat16(r0), __float2bfloat16(r1));
    h2 = *reinterpret_cast<uint32_t*>(&H);
    l2 = *reinterpret_cast<uint32_t*>(&L);
}
// gate order i(0) -> g(2) -> f(1) -> o(3)
__device__ __forceinline__ int gate_of(int cc) {
    return (cc == 0) ? 0 : (cc == 1) ? 2 : (cc == 2) ? 1 : 3;
}

// ---------------------------------------------------------------------------
// recurrent HMMA kernel: 1 CTA = 64 rows, 256 threads, 2 CTAs/SM
// ---------------------------------------------------------------------------
__global__ __launch_bounds__(NTH, 2)
void rnn_tc_kernel(const float* __restrict__ out_w, float* __restrict__ out_enc) {
    extern __shared__ char smem_c[];
    const uint32_t smem_base = smem_u32(smem_c);
    const int tid = threadIdx.x;
    const int wid = tid >> 5;
    const int lane = tid & 31;
    const int mw = wid & 1;        // 2 m-warps (rows 32*mw..)
    const int nw = wid >> 1;       // 4 n-warps (16 chunk-cols each)
    const int b0 = blockIdx.x * BM;

    float* bias_s = (float*)(smem_c + SM_BIAS);
    for (int i = tid; i < NG; i += NTH) bias_s[i] = g_bias[i];
    {   // zero A_HI + A_LO once ((29696+17408)/16 = 2944 uint4)
        uint4 z = make_uint4(0, 0, 0, 0);
        uint4* a4 = (uint4*)(smem_c + SM_A_HI);
        for (int i = tid; i < 2944; i += NTH) a4[i] = z;
    }

    // ldmatrix lane bases
    const uint32_t aHiB = smem_base + SM_A_HI + (mw * 32 + (lane & 15)) * AST
                        + ((lane >> 4) & 1) * 16;
    const uint32_t aLoB = smem_base + SM_A_LO + (mw * 32 + (lane & 15)) * ALST
                        + ((lane >> 4) & 1) * 16;
    const int brow = (lane & 7) + ((lane >> 4) & 1) * 8;   // 16 B-rows for x4
    const int bcol = ((lane >> 3) & 1) * 16;
    const uint32_t bwHiB = smem_base + SM_BW_HI + (nw * 16 + brow) * BSTW + bcol;
    const uint32_t bwLoB = bwHiB + (SM_BW_LO - SM_BW_HI);
    const uint32_t bhHiB = smem_base + SM_BH_HI + (nw * 16 + brow) * BSTH + bcol;
    const uint32_t bhLoB = bhHiB + (SM_BH_LO - SM_BH_HI);

    // per-thread state: [ch][im][rh][in][pair]
    float c_r[2][2][2][2][2];
    float tmp[2][2][2][2][2];
#pragma unroll
    for (int a = 0; a < 2; a++)
#pragma unroll
        for (int b = 0; b < 2; b++)
#pragma unroll
            for (int c = 0; c < 2; c++)
#pragma unroll
                for (int d = 0; d < 2; d++) {
                    c_r[a][b][c][d][0] = 0.f; c_r[a][b][c][d][1] = 0.f;
                }

    for (int t = 0; t < TT; t++) {
        __syncthreads();
        // stage w_in A tile for step t (cols 0..81, pad zero)
        for (int p = tid; p < BM * 41; p += NTH) {
            int m = p / 41;
            int d = (p - m * 41) * 2;
            const float* src = out_w + (((size_t)(b0 + m)) * TT + t) * DD + d;
            float v0 = src[0];
            float v1 = (d + 1 < DD) ? src[1] : 0.f;
            uint32_t h2, l2;
            split_pack(v0, v1, h2, l2);
            *(uint32_t*)(smem_c + SM_A_HI + m * AST + d * 2) = h2;   // 2-term: lo unused
        }

#pragma unroll 1
        for (int cc = 0; cc < 4; cc++) {
            const int q = gate_of(cc);
#pragma unroll 1
            for (int ch = 0; ch < 2; ch++) {
                const int nrow0 = q * HH + ch * 64;   // first weight row of chunk

                // ---- stage B chunk: w_in part + h part, one wait ----
                __syncthreads();   // previous chunk's B readers done
#pragma unroll
                for (int it = 0; it < 6; it++) {      // w_in: 64*12=768 x2
                    int i = it * NTH + tid;
                    if (i < 768) {
                        int n = i / 12, ck = i - n * 12;
                        size_t sb = ((size_t)(nrow0 + n) * KT) * 2 + ck * 16;
                        cp16(smem_base + SM_BW_HI + n * BSTW + ck * 16, (const char*)g_Bh + sb);
                        cp16(smem_base + SM_BW_LO + n * BSTW + ck * 16, (const char*)g_Bl + sb);
                    }
                }
                if (t > 0) {
#pragma unroll
                    for (int it = 0; it < 4; it++) {  // h: 64*16=1024 x2
                        int i = it * NTH + tid;
                        int n = i >> 4, ck = i & 15;
                        size_t sb = ((size_t)(nrow0 + n) * KT + KW) * 2 + ck * 16;
                        cp16(smem_base + SM_BH_HI + n * BSTH + ck * 16, (const char*)g_Bh + sb);
                        cp16(smem_base + SM_BH_LO + n * BSTH + ck * 16, (const char*)g_Bl + sb);
                    }
                }
                cp_wait0();
                __syncthreads();

                // ---- GEMMs ----
                float acc[2][2][4];
#pragma unroll
                for (int im = 0; im < 2; im++)
#pragma unroll
                    for (int in = 0; in < 2; in++)
#pragma unroll
                        for (int r = 0; r < 4; r++) acc[im][in][r] = 0.f;

                // w_in phase: 2-term (A_hi * (B_hi + B_lo)), k 0..95
#pragma unroll 1
                for (int j = 0; j < KW / 16; j++) {
                    uint32_t bh[4], bl[4];
                    ldsm_x4(bwHiB + j * 32, bh);
                    ldsm_x4(bwLoB + j * 32, bl);
#pragma unroll
                    for (int im = 0; im < 2; im++) {
                        uint32_t ah[4];
                        ldsm_x4(aHiB + im * 16 * AST + j * 32, ah);
                        mma16816(acc[im][0], ah, bh);
                        mma16816(acc[im][0], ah, bl);
                        mma16816(acc[im][1], ah, bh + 2);
                        mma16816(acc[im][1], ah, bl + 2);
                    }
                }
                // h phase: 3-term, k 0..127 (A_HI offset 192, A_LO base)
                if (t > 0) {
#pragma unroll 1
                    for (int j = 0; j < HH / 16; j++) {
                        uint32_t bh[4], bl[4];
                        ldsm_x4(bhHiB + j * 32, bh);
                        ldsm_x4(bhLoB + j * 32, bl);
#pragma unroll
                        for (int im = 0; im < 2; im++) {
                            uint32_t ah[4], al[4];
                            ldsm_x4(aHiB + 192 + im * 16 * AST + j * 32, ah);
                            ldsm_x4(aLoB + im * 16 * ALST + j * 32, al);
                            mma16816(acc[im][0], ah, bh);
                            mma16816(acc[im][0], ah, bl);
                            mma16816(acc[im][0], al, bh);
                            mma16816(acc[im][1], ah, bh + 2);
                            mma16816(acc[im][1], ah, bl + 2);
                            mma16816(acc[im][1], al, bh + 2);
                        }
                    }
                }
                __syncthreads();   // B (and A-h) readers done

                // ---- elementwise on (q, ch) ----
#pragma unroll
                for (int im = 0; im < 2; im++) {
#pragma unroll
                    for (int in = 0; in < 2; in++) {
#pragma unroll
                        for (int rh = 0; rh < 2; rh++) {
                            const int m = mw * 32 + im * 16 + (lane >> 2) + rh * 8;
                            const int nl = nw * 16 + in * 8 + (lane & 3) * 2;
                            const int nh = ch * 64 + nl;
                            float g0 = acc[im][in][rh * 2]     + bias_s[q * HH + nh];
                            float g1 = acc[im][in][rh * 2 + 1] + bias_s[q * HH + nh + 1];
                            if (q == 0) {
                                tmp[ch][im][rh][in][0] = sigmoidf_(g0);
                                tmp[ch][im][rh][in][1] = sigmoidf_(g1);
                            } else if (q == 2) {
                                tmp[ch][im][rh][in][0] *= tanhf_(g0);
                                tmp[ch][im][rh][in][1] *= tanhf_(g1);
                            } else if (q == 1) {
                                c_r[ch][im][rh][in][0] =
                                    sigmoidf_(g0) * c_r[ch][im][rh][in][0] + tmp[ch][im][rh][in][0];
                                c_r[ch][im][rh][in][1] =
                                    sigmoidf_(g1) * c_r[ch][im][rh][in][1] + tmp[ch][im][rh][in][1];
                            } else {
                                float h0 = sigmoidf_(g0) * tanhf_(c_r[ch][im][rh][in][0]);
                                float h1 = sigmoidf_(g1) * tanhf_(c_r[ch][im][rh][in][1]);
                                *(float2*)(out_enc + (((size_t)(b0 + m)) * TT + t) * HH + nh) =
                                    make_float2(h0, h1);
                                if (ch == 0) {
                                    // hold: chunk1's h-GEMM still needs old h in A
                                    tmp[0][im][rh][in][0] = h0;
                                    tmp[0][im][rh][in][1] = h1;
                                } else if (t + 1 < TT) {
                                    uint32_t h2, l2;
                                    split_pack(h0, h1, h2, l2);
                                    *(uint32_t*)(smem_c + SM_A_HI + m * AST + (KW + nh) * 2) = h2;
                                    *(uint32_t*)(smem_c + SM_A_LO + m * ALST + nh * 2) = l2;
                                }
                            }
                        }
                    }
                }
                // flush held chunk-0 h after chunk-1's GEMM has read old h
                if (q == 3 && ch == 1 && t + 1 < TT) {
#pragma unroll
                    for (int im = 0; im < 2; im++)
#pragma unroll
                        for (int in = 0; in < 2; in++)
#pragma unroll
                            for (int rh = 0; rh < 2; rh++) {
                                const int m = mw * 32 + im * 16 + (lane >> 2) + rh * 8;
                                const int nl = nw * 16 + in * 8 + (lane & 3) * 2;
                                uint32_t h2, l2;
                                split_pack(tmp[0][im][rh][in][0], tmp[0][im][rh][in][1], h2, l2);
                                *(uint32_t*)(smem_c + SM_A_HI + m * AST + (KW + nl) * 2) = h2;
                                *(uint32_t*)(smem_c + SM_A_LO + m * ALST + nl * 2) = l2;
                            }
                }
            }
        }
    }
}

// ---------------------------------------------------------------------------
extern "C" void kernel_launch(void* const* d_in, const int* in_sizes, int n_in,
                              void* d_out, int out_size) {
    const float* x      = (const float*)d_in[0];
    const float* W_attn = (const float*)d_in[1];
    // d_in[2] = b_attn: cancels in softmax, unused
    const float* W_ih   = (const float*)d_in[3];
    const float* W_hh   = (const float*)d_in[4];
    const float* b_ih   = (const float*)d_in[5];
    const float* b_hh   = (const float*)d_in[6];

    float* out     = (float*)d_out;
    float* out_w   = out;                           // (B, 9, 81)
    float* out_enc = out + (size_t)NB * TT * DD;    // (B, 9, 128)

    prep_kernel<<<448, 256>>>(W_ih, W_hh, b_ih, b_hh);
    attn_kernel<<<NB / 8, 256>>>(x, W_attn, out_w);

    cudaFuncSetAttribute(rnn_tc_kernel, cudaFuncAttributeMaxDynamicSharedMemorySize, SM_TOTAL);
    rnn_tc_kernel<<<NB / BM, NTH, SM_TOTAL>>>(out_w, out_enc);
}

// round 13
// speedup vs baseline: 1.6431x; 1.6431x over previous
#include <cuda_runtime.h>
#include <cuda_bf16.h>
#include <cstdint>
#include <math.h>

// Problem constants
#define NB 32768   // batch
#define TT 9       // time steps (T-1)
#define DD 81      // input dim
#define HH 128     // hidden
#define NG 512     // 4*HH gates
#define KW 96      // w_in K padded (81 -> 96)
#define KT 224     // weight k-cols (96 w_in + 128 h)

// Tiling: BM=128 rows/CTA (256 CTAs), 512 threads = 16 warps (4m x 4n),
// warp tile 32m x 32n, per-thread frag 2x4x4.
#define BM 128
#define NTH 512
#define AST 464    // A row stride bytes (224 bf16; 464%128=80 -> conflict-free)
#define BST 272    // B stage row stride bytes (<=128 bf16; 272%128=16 -> conflict-free)

// SMEM map (bytes) — identical to the 803us R5 kernel
#define SM_BIAS 0          // 2048
#define SM_A_HI 2048       // 128*464 = 59392
#define SM_A_LO 61440      // 59392
#define SM_B_HI 120832     // 128*272 = 34816
#define SM_B_LO 155648     // 34816
#define SM_TOTAL 190464

// device scratch: weights pre-split bf16 hi/lo, row-major [n][224]
__device__ __align__(16) __nv_bfloat16 g_Bh[NG * KT];
__device__ __align__(16) __nv_bfloat16 g_Bl[NG * KT];
__device__ float g_bias[NG];

// ---------------------------------------------------------------------------
// prep: split weights into bf16 hi/lo, layout [n][k=224]; fuse biases.
// ---------------------------------------------------------------------------
__global__ void prep_kernel(const float* __restrict__ W_ih,
                            const float* __restrict__ W_hh,
                            const float* __restrict__ b_ih,
                            const float* __restrict__ b_hh) {
    int idx = blockIdx.x * blockDim.x + threadIdx.x;   // 512*224 = 114688
    if (idx < NG * KT) {
        int n = idx / KT;
        int k = idx - n * KT;
        float w = 0.f;
        if (k < DD) w = W_ih[n * DD + k];
        else if (k >= KW) w = W_hh[n * HH + (k - KW)];
        __nv_bfloat16 hi = __float2bfloat16(w);
        g_Bh[idx] = hi;
        g_Bl[idx] = __float2bfloat16(w - __bfloat162float(hi));
    }
    if (idx < NG) g_bias[idx] = b_ih[idx] + b_hh[idx];
}

// ---------------------------------------------------------------------------
// attention: softmax over d of (sum_t x[b,t,d]*Wx[t]); write input_weighted.
// ---------------------------------------------------------------------------
__global__ void attn_kernel(const float* __restrict__ x,
                            const float* __restrict__ W_attn,
                            float* __restrict__ out_w) {
    int gw = (blockIdx.x * blockDim.x + threadIdx.x) >> 5;
    int lane = threadIdx.x & 31;
    if (gw >= NB) return;

    float wx[TT];
#pragma unroll
    for (int tt = 0; tt < TT; tt++) wx[tt] = W_attn[2 * HH + tt];

    const float* xb = x + (size_t)gw * TT * DD;
    float xr[3][TT];
    float pre[3];
#pragma unroll
    for (int ii = 0; ii < 3; ii++) {
        int d = lane + 32 * ii;
        float p = 0.f;
#pragma unroll
        for (int tt = 0; tt < TT; tt++) {
            float v = (d < DD) ? xb[tt * DD + d] : 0.f;
            xr[ii][tt] = v;
            p = fmaf(v, wx[tt], p);
        }
        pre[ii] = (d < DD) ? p : -3.0e38f;
    }
    float mx = fmaxf(pre[0], fmaxf(pre[1], pre[2]));
#pragma unroll
    for (int o = 16; o > 0; o >>= 1) mx = fmaxf(mx, __shfl_xor_sync(0xffffffffu, mx, o));

    float ev[3];
    float s = 0.f;
#pragma unroll
    for (int ii = 0; ii < 3; ii++) {
        int d = lane + 32 * ii;
        ev[ii] = (d < DD) ? __expf(pre[ii] - mx) : 0.f;
        s += ev[ii];
    }
#pragma unroll
    for (int o = 16; o > 0; o >>= 1) s += __shfl_xor_sync(0xffffffffu, s, o);
    float inv = 1.f / s;

    float* ob = out_w + (size_t)gw * TT * DD;
#pragma unroll
    for (int ii = 0; ii < 3; ii++) {
        int d = lane + 32 * ii;
        if (d < DD) {
            float a = ev[ii] * inv;
#pragma unroll
            for (int tt = 0; tt < TT; tt++) ob[tt * DD + d] = a * xr[ii][tt];
        }
    }
}

// ---------------------------------------------------------------------------
// helpers
// ---------------------------------------------------------------------------
__device__ __forceinline__ uint32_t smem_u32(const void* p) {
    uint32_t a;
    asm("{ .reg .u64 t; cvta.to.shared.u64 t, %1; cvt.u32.u64 %0, t; }" : "=r"(a) : "l"(p));
    return a;
}
__device__ __forceinline__ void ldsm_x4(uint32_t addr, uint32_t* r) {
    asm volatile("ldmatrix.sync.aligned.m8n8.x4.shared.b16 {%0,%1,%2,%3}, [%4];"
                 : "=r"(r[0]), "=r"(r[1]), "=r"(r[2]), "=r"(r[3]) : "r"(addr));
}
__device__ __forceinline__ void mma16816(float* d, const uint32_t* a, const uint32_t* b) {
    asm volatile(
        "mma.sync.aligned.m16n8k16.row.col.f32.bf16.bf16.f32 "
        "{%0,%1,%2,%3}, {%4,%5,%6,%7}, {%8,%9}, {%0,%1,%2,%3};"
        : "+f"(d[0]), "+f"(d[1]), "+f"(d[2]), "+f"(d[3])
        : "r"(a[0]), "r"(a[1]), "r"(a[2]), "r"(a[3]), "r"(b[0]), "r"(b[1]));
}
__device__ __forceinline__ void cp16(uint32_t dst, const void* src) {
    asm volatile("cp.async.cg.shared.global [%0], [%1], 16;"
                 :: "r"(dst), "l"(__cvta_generic_to_global(src)) : "memory");
}
__device__ __forceinline__ void cp_wait0() {
    asm volatile("cp.async.commit_group;" ::: "memory");
    asm volatile("cp.async.wait_group 0;" ::: "memory");
}
__device__ __forceinline__ float sigmoidf_(float v) {
    return __fdividef(1.f, 1.f + __expf(-v));
}
__device__ __forceinline__ float tanhf_(float v) {
    return __fdividef(2.f, 1.f + __expf(-2.f * v)) - 1.f;
}
__device__ __forceinline__ void split_pack(float v0, float v1, uint32_t& h2, uint32_t& l2) {
    __nv_bfloat16 h0 = __float2bfloat16(v0);
    __nv_bfloat16 h1 = __float2bfloat16(v1);
    float r0 = v0 - __bfloat162float(h0);
    float r1 = v1 - __bfloat162float(h1);
    __nv_bfloat162 H(h0, h1);
    __nv_bfloat162 L(__float2bfloat16(r0), __float2bfloat16(r1));
    h2 = *reinterpret_cast<uint32_t*>(&H);
    l2 = *reinterpret_cast<uint32_t*>(&L);
}
// gate order i(0) -> g(2) -> f(1) -> o(3)
__device__ __forceinline__ int gate_of(int cc) {
    return (cc == 0) ? 0 : (cc == 1) ? 2 : (cc == 2) ? 1 : 3;
}

// 3-term GEMM phase: 2 m-tiles x 4 n-tiles per thread
__device__ __forceinline__ void mma_phase3(float acc[2][4][4],
                                           uint32_t aHi, uint32_t aLo,
                                           uint32_t bHi, uint32_t bLo,
                                           int nsteps) {
#pragma unroll 1
    for (int j = 0; j < nsteps; j++) {
        uint32_t bh[4][2], bl[4][2];
#pragma unroll
        for (int pr = 0; pr < 2; pr++) {
            uint32_t r4[4];
            ldsm_x4(bHi + pr * 16 * BST + j * 32, r4);
            bh[pr * 2][0] = r4[0]; bh[pr * 2][1] = r4[1];
            bh[pr * 2 + 1][0] = r4[2]; bh[pr * 2 + 1][1] = r4[3];
            ldsm_x4(bLo + pr * 16 * BST + j * 32, r4);
            bl[pr * 2][0] = r4[0]; bl[pr * 2][1] = r4[1];
            bl[pr * 2 + 1][0] = r4[2]; bl[pr * 2 + 1][1] = r4[3];
        }
#pragma unroll
        for (int im = 0; im < 2; im++) {
            uint32_t ah[4], al[4];
            ldsm_x4(aHi + im * 16 * AST + j * 32, ah);
            ldsm_x4(aLo + im * 16 * AST + j * 32, al);
#pragma unroll
            for (int in = 0; in < 4; in++) {
                mma16816(acc[im][in], ah, bh[in]);
                mma16816(acc[im][in], ah, bl[in]);
                mma16816(acc[im][in], al, bh[in]);
            }
        }
    }
}
// 2-term GEMM phase (w_in): A_hi * (B_hi + B_lo)
__device__ __forceinline__ void mma_phase2(float acc[2][4][4],
                                           uint32_t aHi,
                                           uint32_t bHi, uint32_t bLo,
                                           int nsteps) {
#pragma unroll 1
    for (int j = 0; j < nsteps; j++) {
        uint32_t bh[4][2], bl[4][2];
#pragma unroll
        for (int pr = 0; pr < 2; pr++) {
            uint32_t r4[4];
            ldsm_x4(bHi + pr * 16 * BST + j * 32, r4);
            bh[pr * 2][0] = r4[0]; bh[pr * 2][1] = r4[1];
            bh[pr * 2 + 1][0] = r4[2]; bh[pr * 2 + 1][1] = r4[3];
            ldsm_x4(bLo + pr * 16 * BST + j * 32, r4);
            bl[pr * 2][0] = r4[0]; bl[pr * 2][1] = r4[1];
            bl[pr * 2 + 1][0] = r4[2]; bl[pr * 2 + 1][1] = r4[3];
        }
#pragma unroll
        for (int im = 0; im < 2; im++) {
            uint32_t ah[4];
            ldsm_x4(aHi + im * 16 * AST + j * 32, ah);
#pragma unroll
            for (int in = 0; in < 4; in++) {
                mma16816(acc[im][in], ah, bh[in]);
                mma16816(acc[im][in], ah, bl[in]);
            }
        }
    }
}

// ---------------------------------------------------------------------------
// recurrent HMMA kernel: 1 CTA = 128 rows, 512 threads (16 warps)
// ---------------------------------------------------------------------------
__global__ __launch_bounds__(NTH, 1)
void rnn_tc_kernel(const float* __restrict__ out_w, float* __restrict__ out_enc) {
    extern __shared__ char smem_c[];
    const uint32_t smem_base = smem_u32(smem_c);
    const int tid = threadIdx.x;
    const int wid = tid >> 5;
    const int lane = tid & 31;
    const int mw = wid & 3;        // 4 m-warps (rows 32*mw..)
    const int nw = wid >> 2;       // 4 n-warps (cols 32*nw..)
    const int b0 = blockIdx.x * BM;

    float* bias_s = (float*)(smem_c + SM_BIAS);
    for (int i = tid; i < NG; i += NTH) bias_s[i] = g_bias[i];
    {   // zero A hi+lo: 2*59392/16 = 7424 uint4
        uint4 z = make_uint4(0, 0, 0, 0);
        uint4* a4 = (uint4*)(smem_c + SM_A_HI);
        for (int i = tid; i < 7424; i += NTH) a4[i] = z;
    }

    // lane-resolved ldmatrix bases
    const uint32_t aHiB = smem_base + SM_A_HI + (mw * 32 + (lane & 15)) * AST
                        + ((lane >> 4) & 1) * 16;
    const uint32_t aLoB = aHiB + (SM_A_LO - SM_A_HI);
    const int brow = (lane & 7) + ((lane >> 4) & 1) * 8;
    const uint32_t bHiB = smem_base + SM_B_HI + (nw * 32 + brow) * BST
                        + ((lane >> 3) & 1) * 16;
    const uint32_t bLoB = bHiB + (SM_B_LO - SM_B_HI);

    float c_r[2][4][4];
    float tmp[2][4][4];
#pragma unroll
    for (int im = 0; im < 2; im++)
#pragma unroll
        for (int in = 0; in < 4; in++)
#pragma unroll
            for (int r = 0; r < 4; r++) c_r[im][in][r] = 0.f;

    for (int t = 0; t < TT; t++) {
        __syncthreads();   // prev step A readers done before w_in overwrite
        // stage w_in A tile for step t into A_HI cols [0,82) (2-term: no lo)
        for (int p = tid; p < BM * 41; p += NTH) {
            int m = p / 41;
            int d = (p - m * 41) * 2;
            const float* src = out_w + (((size_t)(b0 + m)) * TT + t) * DD + d;
            float v0 = src[0];
            float v1 = (d + 1 < DD) ? src[1] : 0.f;
            __nv_bfloat162 H(__float2bfloat16(v0), __float2bfloat16(v1));
            *(uint32_t*)(smem_c + SM_A_HI + m * AST + d * 2) =
                *reinterpret_cast<uint32_t*>(&H);
        }

#pragma unroll 1
        for (int cc = 0; cc < 4; cc++) {
            const int q = gate_of(cc);

            float acc[2][4][4];
#pragma unroll
            for (int im = 0; im < 2; im++)
#pragma unroll
                for (int in = 0; in < 4; in++)
#pragma unroll
                    for (int r = 0; r < 4; r++) acc[im][in][r] = 0.f;

            // ---- phase 0: w_in GEMM (k 0..95), 2-term ----
            __syncthreads();   // previous B readers done before overwrite
            for (int it = 0; it < 3; it++) {       // 128*12 = 1536 rows-of-16B
                int i = it * NTH + tid;
                int n = i / 12, ck = i - n * 12;
                size_t sb = ((size_t)(q * HH + n) * KT) * 2 + ck * 16;
                cp16(smem_base + SM_B_HI + n * BST + ck * 16, (const char*)g_Bh + sb);
                cp16(smem_base + SM_B_LO + n * BST + ck * 16, (const char*)g_Bl + sb);
            }
            cp_wait0();
            __syncthreads();
            mma_phase2(acc, aHiB, bHiB, bLoB, KW / 16);

            // ---- phase 1: h GEMM (k 96..223), 3-term, skip at t=0 ----
            if (t > 0) {
                __syncthreads();           // w_in B readers done
                for (int it = 0; it < 4; it++) {   // 128*16 = 2048
                    int i = it * NTH + tid;
                    int n = i >> 4, ck = i & 15;
                    size_t sb = ((size_t)(q * HH + n) * KT + KW) * 2 + ck * 16;
                    cp16(smem_base + SM_B_HI + n * BST + ck * 16, (const char*)g_Bh + sb);
                    cp16(smem_base + SM_B_LO + n * BST + ck * 16, (const char*)g_Bl + sb);
                }
                cp_wait0();
                __syncthreads();
                mma_phase3(acc, aHiB + KW * 2, aLoB + KW * 2, bHiB, bLoB, HH / 16);
            }

            if (q == 3) __syncthreads();   // all h-GEMM A reads done before h overwrite

            // ---- elementwise on gate q ----
#pragma unroll
            for (int im = 0; im < 2; im++) {
#pragma unroll
                for (int in = 0; in < 4; in++) {
#pragma unroll
                    for (int rh = 0; rh < 2; rh++) {
                        const int m = mw * 32 + im * 16 + (lane >> 2) + rh * 8;
                        const int n0 = nw * 32 + in * 8 + (lane & 3) * 2;
                        float g0 = acc[im][in][rh * 2]     + bias_s[q * HH + n0];
                        float g1 = acc[im][in][rh * 2 + 1] + bias_s[q * HH + n0 + 1];
                        if (q == 0) {
                            tmp[im][in][rh * 2]     = sigmoidf_(g0);
                            tmp[im][in][rh * 2 + 1] = sigmoidf_(g1);
                        } else if (q == 2) {
                            tmp[im][in][rh * 2]     *= tanhf_(g0);
                            tmp[im][in][rh * 2 + 1] *= tanhf_(g1);
                        } else if (q == 1) {
                            c_r[im][in][rh * 2] =
                                sigmoidf_(g0) * c_r[im][in][rh * 2] + tmp[im][in][rh * 2];
                            c_r[im][in][rh * 2 + 1] =
                                sigmoidf_(g1) * c_r[im][in][rh * 2 + 1] + tmp[im][in][rh * 2 + 1];
                        } else {
                            float h0 = sigmoidf_(g0) * tanhf_(c_r[im][in][rh * 2]);
                            float h1 = sigmoidf_(g1) * tanhf_(c_r[im][in][rh * 2 + 1]);
                            *(float2*)(out_enc + (((size_t)(b0 + m)) * TT + t) * HH + n0) =
                                make_float2(h0, h1);
                            if (t + 1 < TT) {
                                uint32_t h2, l2;
                                split_pack(h0, h1, h2, l2);
                                *(uint32_t*)(smem_c + SM_A_HI + m * AST + (KW + n0) * 2) = h2;
                                *(uint32_t*)(smem_c + SM_A_LO + m * AST + (KW + n0) * 2) = l2;
                            }
                        }
                    }
                }
            }
        }
    }
}

// ---------------------------------------------------------------------------
extern "C" void kernel_launch(void* const* d_in, const int* in_sizes, int n_in,
                              void* d_out, int out_size) {
    const float* x      = (const float*)d_in[0];
    const float* W_attn = (const float*)d_in[1];
    // d_in[2] = b_attn: cancels in softmax, unused
    const float* W_ih   = (const float*)d_in[3];
    const float* W_hh   = (const float*)d_in[4];
    const float* b_ih   = (const float*)d_in[5];
    const float* b_hh   = (const float*)d_in[6];

    float* out     = (float*)d_out;
    float* out_w   = out;                           // (B, 9, 81)
    float* out_enc = out + (size_t)NB * TT * DD;    // (B, 9, 128)

    prep_kernel<<<448, 256>>>(W_ih, W_hh, b_ih, b_hh);
    attn_kernel<<<NB / 8, 256>>>(x, W_attn, out_w);

    cudaFuncSetAttribute(rnn_tc_kernel, cudaFuncAttributeMaxDynamicSharedMemorySize, SM_TOTAL);
    rnn_tc_kernel<<<NB / BM, NTH, SM_TOTAL>>>(out_w, out_enc);
}

// round 14
// speedup vs baseline: 1.8021x; 1.0967x over previous
#include <cuda_runtime.h>
#include <cuda_bf16.h>
#include <cstdint>
#include <math.h>

// Problem constants
#define NB 32768   // batch
#define TT 9       // time steps (T-1)
#define DD 81      // input dim
#define HH 128     // hidden
#define NG 512     // 4*HH gates
#define KW 96      // w_in K padded (81 -> 96)
#define KT 224     // weight k-cols (96 w_in + 128 h)

// Tiling: BM=128 rows/CTA (256 CTAs), 512 threads = 16 warps (4m x 4n)
#define BM 128
#define NTH 512
#define AST 464    // A_HI row stride bytes (224 bf16; 464%128=80 -> conflict-free)
#define ALST 272   // A_LO row stride bytes (h cols only; 272%128=16 -> conflict-free)
#define BSTW 208   // B w_in region stride (96 bf16 used; 208%128=80 -> ok)
#define BSTH 272   // B h region stride (128 bf16 used)

// SMEM map (bytes) — 219136 total
#define SM_BIAS  0         // 2048
#define SM_A_HI  2048      // 128*464 = 59392
#define SM_A_LO  61440     // 128*272 = 34816 (h cols only)
#define SM_BW_HI 96256     // 128*208 = 26624
#define SM_BW_LO 122880    // 26624
#define SM_BH_HI 149504    // 128*272 = 34816
#define SM_BH_LO 184320    // 34816
#define SM_TOTAL 219136

// device scratch: weights pre-split bf16 hi/lo, row-major [n][224]
__device__ __align__(16) __nv_bfloat16 g_Bh[NG * KT];
__device__ __align__(16) __nv_bfloat16 g_Bl[NG * KT];
__device__ float g_bias[NG];

// ---------------------------------------------------------------------------
// prep: split weights into bf16 hi/lo, layout [n][k=224]; fuse biases.
// ---------------------------------------------------------------------------
__global__ void prep_kernel(const float* __restrict__ W_ih,
                            const float* __restrict__ W_hh,
                            const float* __restrict__ b_ih,
                            const float* __restrict__ b_hh) {
    int idx = blockIdx.x * blockDim.x + threadIdx.x;   // 512*224 = 114688
    if (idx < NG * KT) {
        int n = idx / KT;
        int k = idx - n * KT;
        float w = 0.f;
        if (k < DD) w = W_ih[n * DD + k];
        else if (k >= KW) w = W_hh[n * HH + (k - KW)];
        __nv_bfloat16 hi = __float2bfloat16(w);
        g_Bh[idx] = hi;
        g_Bl[idx] = __float2bfloat16(w - __bfloat162float(hi));
    }
    if (idx < NG) g_bias[idx] = b_ih[idx] + b_hh[idx];
}

// ---------------------------------------------------------------------------
// attention: softmax over d of (sum_t x[b,t,d]*Wx[t]); write input_weighted.
// ---------------------------------------------------------------------------
__global__ void attn_kernel(const float* __restrict__ x,
                            const float* __restrict__ W_attn,
                            float* __restrict__ out_w) {
    int gw = (blockIdx.x * blockDim.x + threadIdx.x) >> 5;
    int lane = threadIdx.x & 31;
    if (gw >= NB) return;

    float wx[TT];
#pragma unroll
    for (int tt = 0; tt < TT; tt++) wx[tt] = W_attn[2 * HH + tt];

    const float* xb = x + (size_t)gw * TT * DD;
    float xr[3][TT];
    float pre[3];
#pragma unroll
    for (int ii = 0; ii < 3; ii++) {
        int d = lane + 32 * ii;
        float p = 0.f;
#pragma unroll
        for (int tt = 0; tt < TT; tt++) {
            float v = (d < DD) ? xb[tt * DD + d] : 0.f;
            xr[ii][tt] = v;
            p = fmaf(v, wx[tt], p);
        }
        pre[ii] = (d < DD) ? p : -3.0e38f;
    }
    float mx = fmaxf(pre[0], fmaxf(pre[1], pre[2]));
#pragma unroll
    for (int o = 16; o > 0; o >>= 1) mx = fmaxf(mx, __shfl_xor_sync(0xffffffffu, mx, o));

    float ev[3];
    float s = 0.f;
#pragma unroll
    for (int ii = 0; ii < 3; ii++) {
        int d = lane + 32 * ii;
        ev[ii] = (d < DD) ? __expf(pre[ii] - mx) : 0.f;
        s += ev[ii];
    }
#pragma unroll
    for (int o = 16; o > 0; o >>= 1) s += __shfl_xor_sync(0xffffffffu, s, o);
    float inv = 1.f / s;

    float* ob = out_w + (size_t)gw * TT * DD;
#pragma unroll
    for (int ii = 0; ii < 3; ii++) {
        int d = lane + 32 * ii;
        if (d < DD) {
            float a = ev[ii] * inv;
#pragma unroll
            for (int tt = 0; tt < TT; tt++) ob[tt * DD + d] = a * xr[ii][tt];
        }
    }
}

// ---------------------------------------------------------------------------
// helpers
// ---------------------------------------------------------------------------
__device__ __forceinline__ uint32_t smem_u32(const void* p) {
    uint32_t a;
    asm("{ .reg .u64 t; cvta.to.shared.u64 t, %1; cvt.u32.u64 %0, t; }" : "=r"(a) : "l"(p));
    return a;
}
__device__ __forceinline__ void ldsm_x4(uint32_t addr, uint32_t* r) {
    asm volatile("ldmatrix.sync.aligned.m8n8.x4.shared.b16 {%0,%1,%2,%3}, [%4];"
                 : "=r"(r[0]), "=r"(r[1]), "=r"(r[2]), "=r"(r[3]) : "r"(addr));
}
__device__ __forceinline__ void mma16816(float* d, const uint32_t* a, const uint32_t* b) {
    asm volatile(
        "mma.sync.aligned.m16n8k16.row.col.f32.bf16.bf16.f32 "
        "{%0,%1,%2,%3}, {%4,%5,%6,%7}, {%8,%9}, {%0,%1,%2,%3};"
        : "+f"(d[0]), "+f"(d[1]), "+f"(d[2]), "+f"(d[3])
        : "r"(a[0]), "r"(a[1]), "r"(a[2]), "r"(a[3]), "r"(b[0]), "r"(b[1]));
}
__device__ __forceinline__ void cp16(uint32_t dst, const void* src) {
    asm volatile("cp.async.cg.shared.global [%0], [%1], 16;"
                 :: "r"(dst), "l"(__cvta_generic_to_global(src)) : "memory");
}
__device__ __forceinline__ void cp_commit() {
    asm volatile("cp.async.commit_group;" ::: "memory");
}
__device__ __forceinline__ void cp_waitall() {
    asm volatile("cp.async.wait_group 0;" ::: "memory");
}
__device__ __forceinline__ float tanh_fast(float x) {
    float y;
    asm("tanh.approx.f32 %0, %1;" : "=f"(y) : "f"(x));
    return y;
}
__device__ __forceinline__ float sig_fast(float x) {
    return fmaf(0.5f, tanh_fast(0.5f * x), 0.5f);
}
__device__ __forceinline__ void split_pack(float v0, float v1, uint32_t& h2, uint32_t& l2) {
    __nv_bfloat16 h0 = __float2bfloat16(v0);
    __nv_bfloat16 h1 = __float2bfloat16(v1);
    float r0 = v0 - __bfloat162float(h0);
    float r1 = v1 - __bfloat162float(h1);
    __nv_bfloat162 H(h0, h1);
    __nv_bfloat162 L(__float2bfloat16(r0), __float2bfloat16(r1));
    h2 = *reinterpret_cast<uint32_t*>(&H);
    l2 = *reinterpret_cast<uint32_t*>(&L);
}
// gate order i(0) -> g(2) -> f(1) -> o(3)
__device__ __forceinline__ int gate_of(int cc) {
    return (cc == 0) ? 0 : (cc == 1) ? 2 : (cc == 2) ? 1 : 3;
}

// issue cp.async for stream item s (s = t*4 + cc): w_in part + (t>0) h part
__device__ __forceinline__ void issue_cp(int s, uint32_t smem_base, int tid) {
    const int q = gate_of(s & 3);
#pragma unroll
    for (int it = 0; it < 3; it++) {           // w_in: 128*12 = 1536 16B-chunks
        int i = it * NTH + tid;
        int n = i / 12, ck = i - n * 12;
        size_t sb = ((size_t)(q * HH + n) * KT) * 2 + ck * 16;
        cp16(smem_base + SM_BW_HI + n * BSTW + ck * 16, (const char*)g_Bh + sb);
        cp16(smem_base + SM_BW_LO + n * BSTW + ck * 16, (const char*)g_Bl + sb);
    }
    if (s >= 4) {                              // h part needed only for t>0
#pragma unroll
        for (int it = 0; it < 4; it++) {       // h: 128*16 = 2048
            int i = it * NTH + tid;
            int n = i >> 4, ck = i & 15;
            size_t sb = ((size_t)(q * HH + n) * KT + KW) * 2 + ck * 16;
            cp16(smem_base + SM_BH_HI + n * BSTH + ck * 16, (const char*)g_Bh + sb);
            cp16(smem_base + SM_BH_LO + n * BSTH + ck * 16, (const char*)g_Bl + sb);
        }
    }
    cp_commit();
}

// stage w_in A tile for step t (cols 0..81, bf16 hi only — 2-term split)
__device__ __forceinline__ void stage_win(const float* __restrict__ out_w,
                                          char* smem_c, int b0, int t, int tid) {
    for (int p = tid; p < BM * 41; p += NTH) {
        int m = p / 41;
        int d = (p - m * 41) * 2;
        const float* src = out_w + (((size_t)(b0 + m)) * TT + t) * DD + d;
        float v0 = src[0];
        float v1 = (d + 1 < DD) ? src[1] : 0.f;
        __nv_bfloat162 H(__float2bfloat16(v0), __float2bfloat16(v1));
        *(uint32_t*)(smem_c + SM_A_HI + m * AST + d * 2) =
            *reinterpret_cast<uint32_t*>(&H);
    }
}

// ---------------------------------------------------------------------------
// recurrent HMMA kernel: 1 CTA = 128 rows, 512 threads (16 warps)
// ---------------------------------------------------------------------------
__global__ __launch_bounds__(NTH, 1)
void rnn_tc_kernel(const float* __restrict__ out_w, float* __restrict__ out_enc) {
    extern __shared__ char smem_c[];
    const uint32_t smem_base = smem_u32(smem_c);
    const int tid = threadIdx.x;
    const int wid = tid >> 5;
    const int lane = tid & 31;
    const int mw = wid & 3;        // 4 m-warps (rows 32*mw..)
    const int nw = wid >> 2;       // 4 n-warps (cols 32*nw..)
    const int b0 = blockIdx.x * BM;

    float* bias_s = (float*)(smem_c + SM_BIAS);
    for (int i = tid; i < NG; i += NTH) bias_s[i] = g_bias[i];
    {   // zero A_HI + A_LO: (59392+34816)/16 = 5888 uint4
        uint4 z = make_uint4(0, 0, 0, 0);
        uint4* a4 = (uint4*)(smem_c + SM_A_HI);
        for (int i = tid; i < 5888; i += NTH) a4[i] = z;
    }

    // lane-resolved ldmatrix bases
    const uint32_t aHiB = smem_base + SM_A_HI + (mw * 32 + (lane & 15)) * AST
                        + ((lane >> 4) & 1) * 16;
    const uint32_t aLoB = smem_base + SM_A_LO + (mw * 32 + (lane & 15)) * ALST
                        + ((lane >> 4) & 1) * 16;
    const int brow = (lane & 7) + ((lane >> 4) & 1) * 8;
    const int bcol = ((lane >> 3) & 1) * 16;
    const uint32_t bwHiB = smem_base + SM_BW_HI + (nw * 32 + brow) * BSTW + bcol;
    const uint32_t bwLoB = bwHiB + (SM_BW_LO - SM_BW_HI);
    const uint32_t bhHiB = smem_base + SM_BH_HI + (nw * 32 + brow) * BSTH + bcol;
    const uint32_t bhLoB = bhHiB + (SM_BH_LO - SM_BH_HI);

    float c_r[2][4][4];
    float tmp[2][4][4];
#pragma unroll
    for (int im = 0; im < 2; im++)
#pragma unroll
        for (int in = 0; in < 4; in++)
#pragma unroll
            for (int r = 0; r < 4; r++) c_r[im][in][r] = 0.f;

    // prologue: first gate's B in flight; w_in A for t=0
    issue_cp(0, smem_base, tid);
    stage_win(out_w, smem_c, b0, 0, tid);

#pragma unroll 1
    for (int s = 0; s < 4 * TT; s++) {
        const int t = s >> 2;
        const int q = gate_of(s & 3);

        cp_waitall();
        __syncthreads();     // B ready; A writes (w_in / h) visible to all

        // ---- GEMMs (w_in 2-term, then h 3-term) ----
        float acc[2][4][4];
#pragma unroll
        for (int im = 0; im < 2; im++)
#pragma unroll
            for (int in = 0; in < 4; in++)
#pragma unroll
                for (int r = 0; r < 4; r++) acc[im][in][r] = 0.f;

#pragma unroll 1
        for (int j = 0; j < KW / 16; j++) {
            uint32_t bh[4][2], bl[4][2];
#pragma unroll
            for (int pr = 0; pr < 2; pr++) {
                uint32_t r4[4];
                ldsm_x4(bwHiB + pr * 16 * BSTW + j * 32, r4);
                bh[pr * 2][0] = r4[0]; bh[pr * 2][1] = r4[1];
                bh[pr * 2 + 1][0] = r4[2]; bh[pr * 2 + 1][1] = r4[3];
                ldsm_x4(bwLoB + pr * 16 * BSTW + j * 32, r4);
                bl[pr * 2][0] = r4[0]; bl[pr * 2][1] = r4[1];
                bl[pr * 2 + 1][0] = r4[2]; bl[pr * 2 + 1][1] = r4[3];
            }
#pragma unroll
            for (int im = 0; im < 2; im++) {
                uint32_t ah[4];
                ldsm_x4(aHiB + im * 16 * AST + j * 32, ah);
#pragma unroll
                for (int in = 0; in < 4; in++) {
                    mma16816(acc[im][in], ah, bh[in]);
                    mma16816(acc[im][in], ah, bl[in]);
                }
            }
        }
        if (t > 0) {
#pragma unroll 1
            for (int j = 0; j < HH / 16; j++) {
                uint32_t bh[4][2], bl[4][2];
#pragma unroll
                for (int pr = 0; pr < 2; pr++) {
                    uint32_t r4[4];
                    ldsm_x4(bhHiB + pr * 16 * BSTH + j * 32, r4);
                    bh[pr * 2][0] = r4[0]; bh[pr * 2][1] = r4[1];
                    bh[pr * 2 + 1][0] = r4[2]; bh[pr * 2 + 1][1] = r4[3];
                    ldsm_x4(bhLoB + pr * 16 * BSTH + j * 32, r4);
                    bl[pr * 2][0] = r4[0]; bl[pr * 2][1] = r4[1];
                    bl[pr * 2 + 1][0] = r4[2]; bl[pr * 2 + 1][1] = r4[3];
                }
#pragma unroll
                for (int im = 0; im < 2; im++) {
                    uint32_t ah[4], al[4];
                    ldsm_x4(aHiB + 192 + im * 16 * AST + j * 32, ah);
                    ldsm_x4(aLoB + im * 16 * ALST + j * 32, al);
#pragma unroll
                    for (int in = 0; in < 4; in++) {
                        mma16816(acc[im][in], ah, bh[in]);
                        mma16816(acc[im][in], ah, bl[in]);
                        mma16816(acc[im][in], al, bh[in]);
                    }
                }
            }
        }

        __syncthreads();     // B + A readers done -> safe to restage

        // pipeline: next gate's B in flight; next step's w_in A staged
        if (s + 1 < 4 * TT) issue_cp(s + 1, smem_base, tid);
        if (q == 3 && t + 1 < TT) stage_win(out_w, smem_c, b0, t + 1, tid);

        // ---- elementwise on gate q (overlaps cp flight) ----
#pragma unroll
        for (int im = 0; im < 2; im++) {
#pragma unroll
            for (int in = 0; in < 4; in++) {
#pragma unroll
                for (int rh = 0; rh < 2; rh++) {
                    const int m = mw * 32 + im * 16 + (lane >> 2) + rh * 8;
                    const int n0 = nw * 32 + in * 8 + (lane & 3) * 2;
                    float g0 = acc[im][in][rh * 2]     + bias_s[q * HH + n0];
                    float g1 = acc[im][in][rh * 2 + 1] + bias_s[q * HH + n0 + 1];
                    if (q == 0) {
                        tmp[im][in][rh * 2]     = sig_fast(g0);
                        tmp[im][in][rh * 2 + 1] = sig_fast(g1);
                    } else if (q == 2) {
                        tmp[im][in][rh * 2]     *= tanh_fast(g0);
                        tmp[im][in][rh * 2 + 1] *= tanh_fast(g1);
                    } else if (q == 1) {
                        c_r[im][in][rh * 2] =
                            sig_fast(g0) * c_r[im][in][rh * 2] + tmp[im][in][rh * 2];
                        c_r[im][in][rh * 2 + 1] =
                            sig_fast(g1) * c_r[im][in][rh * 2 + 1] + tmp[im][in][rh * 2 + 1];
                    } else {
                        float h0 = sig_fast(g0) * tanh_fast(c_r[im][in][rh * 2]);
                        float h1 = sig_fast(g1) * tanh_fast(c_r[im][in][rh * 2 + 1]);
                        *(float2*)(out_enc + (((size_t)(b0 + m)) * TT + t) * HH + n0) =
                            make_float2(h0, h1);
                        if (t + 1 < TT) {
                            uint32_t h2, l2;
                            split_pack(h0, h1, h2, l2);
                            *(uint32_t*)(smem_c + SM_A_HI + m * AST + (KW + n0) * 2) = h2;
                            *(uint32_t*)(smem_c + SM_A_LO + m * ALST + n0 * 2) = l2;
                        }
                    }
                }
            }
        }
    }
}

// ---------------------------------------------------------------------------
extern "C" void kernel_launch(void* const* d_in, const int* in_sizes, int n_in,
                              void* d_out, int out_size) {
    const float* x      = (const float*)d_in[0];
    const float* W_attn = (const float*)d_in[1];
    // d_in[2] = b_attn: cancels in softmax, unused
    const float* W_ih   = (const float*)d_in[3];
    const float* W_hh   = (const float*)d_in[4];
    const float* b_ih   = (const float*)d_in[5];
    const float* b_hh   = (const float*)d_in[6];

    float* out     = (float*)d_out;
    float* out_w   = out;                           // (B, 9, 81)
    float* out_enc = out + (size_t)NB * TT * DD;    // (B, 9, 128)

    prep_kernel<<<448, 256>>>(W_ih, W_hh, b_ih, b_hh);
    attn_kernel<<<NB / 8, 256>>>(x, W_attn, out_w);

    cudaFuncSetAttribute(rnn_tc_kernel, cudaFuncAttributeMaxDynamicSharedMemorySize, SM_TOTAL);
    rnn_tc_kernel<<<NB / BM, NTH, SM_TOTAL>>>(out_w, out_enc);
}

// round 15
// speedup vs baseline: 2.0297x; 1.1263x over previous
#include <cuda_runtime.h>
#include <cuda_bf16.h>
#include <cstdint>
#include <math.h>

// Problem constants
#define NB 32768   // batch
#define TT 9       // time steps (T-1)
#define DD 81      // input dim
#define HH 128     // hidden
#define NG 512     // 4*HH gates
#define KW 96      // w_in K padded (81 -> 96)
#define KT 224     // weight k-cols (96 w_in + 128 h)

// Tiling: BM=128 rows/CTA (256 CTAs), 512 threads = 16 warps (4m x 4n)
#define BM 128
#define NTH 512
#define AST 464    // A row stride bytes (224 bf16; 464%128=80 -> conflict-free)
#define BSTW 208   // B w_in region stride (96 bf16 used; 208%128=80 -> ok)
#define BSTH 272   // B h region stride (128 bf16 used; 272%128=16 -> ok)

// SMEM map (bytes) — 184320 total
#define SM_BIAS  0         // 2048
#define SM_A_HI  2048      // 128*464 = 59392 (w_in cols 0..95 | h cols 96..223)
#define SM_BW_HI 61440     // 128*208 = 26624
#define SM_BW_LO 88064     // 26624
#define SM_BH_HI 114688    // 128*272 = 34816
#define SM_BH_LO 149504    // 34816
#define SM_TOTAL 184320

// device scratch: weights pre-split bf16 hi/lo, row-major [n][224]
__device__ __align__(16) __nv_bfloat16 g_Bh[NG * KT];
__device__ __align__(16) __nv_bfloat16 g_Bl[NG * KT];
__device__ float g_bias[NG];

// ---------------------------------------------------------------------------
// prep: split weights into bf16 hi/lo, layout [n][k=224]; fuse biases.
// ---------------------------------------------------------------------------
__global__ void prep_kernel(const float* __restrict__ W_ih,
                            const float* __restrict__ W_hh,
                            const float* __restrict__ b_ih,
                            const float* __restrict__ b_hh) {
    int idx = blockIdx.x * blockDim.x + threadIdx.x;   // 512*224 = 114688
    if (idx < NG * KT) {
        int n = idx / KT;
        int k = idx - n * KT;
        float w = 0.f;
        if (k < DD) w = W_ih[n * DD + k];
        else if (k >= KW) w = W_hh[n * HH + (k - KW)];
        __nv_bfloat16 hi = __float2bfloat16(w);
        g_Bh[idx] = hi;
        g_Bl[idx] = __float2bfloat16(w - __bfloat162float(hi));
    }
    if (idx < NG) g_bias[idx] = b_ih[idx] + b_hh[idx];
}

// ---------------------------------------------------------------------------
// attention: softmax over d of (sum_t x[b,t,d]*Wx[t]); write input_weighted.
// ---------------------------------------------------------------------------
__global__ void attn_kernel(const float* __restrict__ x,
                            const float* __restrict__ W_attn,
                            float* __restrict__ out_w) {
    int gw = (blockIdx.x * blockDim.x + threadIdx.x) >> 5;
    int lane = threadIdx.x & 31;
    if (gw >= NB) return;

    float wx[TT];
#pragma unroll
    for (int tt = 0; tt < TT; tt++) wx[tt] = W_attn[2 * HH + tt];

    const float* xb = x + (size_t)gw * TT * DD;
    float xr[3][TT];
    float pre[3];
#pragma unroll
    for (int ii = 0; ii < 3; ii++) {
        int d = lane + 32 * ii;
        float p = 0.f;
#pragma unroll
        for (int tt = 0; tt < TT; tt++) {
            float v = (d < DD) ? xb[tt * DD + d] : 0.f;
            xr[ii][tt] = v;
            p = fmaf(v, wx[tt], p);
        }
        pre[ii] = (d < DD) ? p : -3.0e38f;
    }
    float mx = fmaxf(pre[0], fmaxf(pre[1], pre[2]));
#pragma unroll
    for (int o = 16; o > 0; o >>= 1) mx = fmaxf(mx, __shfl_xor_sync(0xffffffffu, mx, o));

    float ev[3];
    float s = 0.f;
#pragma unroll
    for (int ii = 0; ii < 3; ii++) {
        int d = lane + 32 * ii;
        ev[ii] = (d < DD) ? __expf(pre[ii] - mx) : 0.f;
        s += ev[ii];
    }
#pragma unroll
    for (int o = 16; o > 0; o >>= 1) s += __shfl_xor_sync(0xffffffffu, s, o);
    float inv = 1.f / s;

    float* ob = out_w + (size_t)gw * TT * DD;
#pragma unroll
    for (int ii = 0; ii < 3; ii++) {
        int d = lane + 32 * ii;
        if (d < DD) {
            float a = ev[ii] * inv;
#pragma unroll
            for (int tt = 0; tt < TT; tt++) ob[tt * DD + d] = a * xr[ii][tt];
        }
    }
}

// ---------------------------------------------------------------------------
// helpers
// ---------------------------------------------------------------------------
__device__ __forceinline__ uint32_t smem_u32(const void* p) {
    uint32_t a;
    asm("{ .reg .u64 t; cvta.to.shared.u64 t, %1; cvt.u32.u64 %0, t; }" : "=r"(a) : "l"(p));
    return a;
}
__device__ __forceinline__ void ldsm_x4(uint32_t addr, uint32_t* r) {
    asm volatile("ldmatrix.sync.aligned.m8n8.x4.shared.b16 {%0,%1,%2,%3}, [%4];"
                 : "=r"(r[0]), "=r"(r[1]), "=r"(r[2]), "=r"(r[3]) : "r"(addr));
}
__device__ __forceinline__ void mma16816(float* d, const uint32_t* a, const uint32_t* b) {
    asm volatile(
        "mma.sync.aligned.m16n8k16.row.col.f32.bf16.bf16.f32 "
        "{%0,%1,%2,%3}, {%4,%5,%6,%7}, {%8,%9}, {%0,%1,%2,%3};"
        : "+f"(d[0]), "+f"(d[1]), "+f"(d[2]), "+f"(d[3])
        : "r"(a[0]), "r"(a[1]), "r"(a[2]), "r"(a[3]), "r"(b[0]), "r"(b[1]));
}
__device__ __forceinline__ void cp16(uint32_t dst, const void* src) {
    asm volatile("cp.async.cg.shared.global [%0], [%1], 16;"
                 :: "r"(dst), "l"(__cvta_generic_to_global(src)) : "memory");
}
__device__ __forceinline__ void cp_commit() {
    asm volatile("cp.async.commit_group;" ::: "memory");
}
__device__ __forceinline__ void cp_waitall() {
    asm volatile("cp.async.wait_group 0;" ::: "memory");
}
__device__ __forceinline__ float tanh_fast(float x) {
    float y;
    asm("tanh.approx.f32 %0, %1;" : "=f"(y) : "f"(x));
    return y;
}
__device__ __forceinline__ float sig_fast(float x) {
    return fmaf(0.5f, tanh_fast(0.5f * x), 0.5f);
}
__device__ __forceinline__ uint32_t pack_bf16x2(float v0, float v1) {
    __nv_bfloat162 H(__float2bfloat16(v0), __float2bfloat16(v1));
    return *reinterpret_cast<uint32_t*>(&H);
}
// gate order i(0) -> g(2) -> f(1) -> o(3)
__device__ __forceinline__ int gate_of(int cc) {
    return (cc == 0) ? 0 : (cc == 1) ? 2 : (cc == 2) ? 1 : 3;
}

// issue cp.async for stream item s (s = t*4 + cc): w_in part + (t>0) h part
__device__ __forceinline__ void issue_cp(int s, uint32_t smem_base, int tid) {
    const int q = gate_of(s & 3);
#pragma unroll
    for (int it = 0; it < 3; it++) {           // w_in: 128*12 = 1536 16B-chunks
        int i = it * NTH + tid;
        int n = i / 12, ck = i - n * 12;
        size_t sb = ((size_t)(q * HH + n) * KT) * 2 + ck * 16;
        cp16(smem_base + SM_BW_HI + n * BSTW + ck * 16, (const char*)g_Bh + sb);
        cp16(smem_base + SM_BW_LO + n * BSTW + ck * 16, (const char*)g_Bl + sb);
    }
    if (s >= 4) {                              // h part needed only for t>0
#pragma unroll
        for (int it = 0; it < 4; it++) {       // h: 128*16 = 2048
            int i = it * NTH + tid;
            int n = i >> 4, ck = i & 15;
            size_t sb = ((size_t)(q * HH + n) * KT + KW) * 2 + ck * 16;
            cp16(smem_base + SM_BH_HI + n * BSTH + ck * 16, (const char*)g_Bh + sb);
            cp16(smem_base + SM_BH_LO + n * BSTH + ck * 16, (const char*)g_Bl + sb);
        }
    }
    cp_commit();
}

// stage w_in A tile for step t (cols 0..81, bf16 hi only — 2-term split)
__device__ __forceinline__ void stage_win(const float* __restrict__ out_w,
                                          char* smem_c, int b0, int t, int tid) {
    for (int p = tid; p < BM * 41; p += NTH) {
        int m = p / 41;
        int d = (p - m * 41) * 2;
        const float* src = out_w + (((size_t)(b0 + m)) * TT + t) * DD + d;
        float v0 = src[0];
        float v1 = (d + 1 < DD) ? src[1] : 0.f;
        *(uint32_t*)(smem_c + SM_A_HI + m * AST + d * 2) = pack_bf16x2(v0, v1);
    }
}

// ---------------------------------------------------------------------------
// recurrent HMMA kernel: 1 CTA = 128 rows, 512 threads (16 warps)
// Both GEMM phases 2-term: A_hi * (B_hi + B_lo). Weight residual compensated;
// activation residual dropped (validated error class, ~1e-4).
// ---------------------------------------------------------------------------
__global__ __launch_bounds__(NTH, 1)
void rnn_tc_kernel(const float* __restrict__ out_w, float* __restrict__ out_enc) {
    extern __shared__ char smem_c[];
    const uint32_t smem_base = smem_u32(smem_c);
    const int tid = threadIdx.x;
    const int wid = tid >> 5;
    const int lane = tid & 31;
    const int mw = wid & 3;        // 4 m-warps (rows 32*mw..)
    const int nw = wid >> 2;       // 4 n-warps (cols 32*nw..)
    const int b0 = blockIdx.x * BM;

    float* bias_s = (float*)(smem_c + SM_BIAS);
    for (int i = tid; i < NG; i += NTH) bias_s[i] = g_bias[i];
    {   // zero A_HI: 59392/16 = 3712 uint4
        uint4 z = make_uint4(0, 0, 0, 0);
        uint4* a4 = (uint4*)(smem_c + SM_A_HI);
        for (int i = tid; i < 3712; i += NTH) a4[i] = z;
    }

    // lane-resolved ldmatrix bases
    const uint32_t aHiB = smem_base + SM_A_HI + (mw * 32 + (lane & 15)) * AST
                        + ((lane >> 4) & 1) * 16;
    const int brow = (lane & 7) + ((lane >> 4) & 1) * 8;
    const int bcol = ((lane >> 3) & 1) * 16;
    const uint32_t bwHiB = smem_base + SM_BW_HI + (nw * 32 + brow) * BSTW + bcol;
    const uint32_t bwLoB = bwHiB + (SM_BW_LO - SM_BW_HI);
    const uint32_t bhHiB = smem_base + SM_BH_HI + (nw * 32 + brow) * BSTH + bcol;
    const uint32_t bhLoB = bhHiB + (SM_BH_LO - SM_BH_HI);

    float c_r[2][4][4];
    float tmp[2][4][4];
#pragma unroll
    for (int im = 0; im < 2; im++)
#pragma unroll
        for (int in = 0; in < 4; in++)
#pragma unroll
            for (int r = 0; r < 4; r++) c_r[im][in][r] = 0.f;

    // prologue: first gate's B in flight; w_in A for t=0
    issue_cp(0, smem_base, tid);
    stage_win(out_w, smem_c, b0, 0, tid);

#pragma unroll 1
    for (int s = 0; s < 4 * TT; s++) {
        const int t = s >> 2;
        const int q = gate_of(s & 3);

        cp_waitall();
        __syncthreads();     // B ready; A writes (w_in / h) visible to all

        // ---- GEMMs: w_in (k 0..95) then h (k 96..223), both 2-term ----
        float acc[2][4][4];
#pragma unroll
        for (int im = 0; im < 2; im++)
#pragma unroll
            for (int in = 0; in < 4; in++)
#pragma unroll
                for (int r = 0; r < 4; r++) acc[im][in][r] = 0.f;

#pragma unroll 1
        for (int j = 0; j < KW / 16; j++) {
            uint32_t bh[4][2], bl[4][2];
#pragma unroll
            for (int pr = 0; pr < 2; pr++) {
                uint32_t r4[4];
                ldsm_x4(bwHiB + pr * 16 * BSTW + j * 32, r4);
                bh[pr * 2][0] = r4[0]; bh[pr * 2][1] = r4[1];
                bh[pr * 2 + 1][0] = r4[2]; bh[pr * 2 + 1][1] = r4[3];
                ldsm_x4(bwLoB + pr * 16 * BSTW + j * 32, r4);
                bl[pr * 2][0] = r4[0]; bl[pr * 2][1] = r4[1];
                bl[pr * 2 + 1][0] = r4[2]; bl[pr * 2 + 1][1] = r4[3];
            }
#pragma unroll
            for (int im = 0; im < 2; im++) {
                uint32_t ah[4];
                ldsm_x4(aHiB + im * 16 * AST + j * 32, ah);
#pragma unroll
                for (int in = 0; in < 4; in++) {
                    mma16816(acc[im][in], ah, bh[in]);
                    mma16816(acc[im][in], ah, bl[in]);
                }
            }
        }
        if (t > 0) {
#pragma unroll 1
            for (int j = 0; j < HH / 16; j++) {
                uint32_t bh[4][2], bl[4][2];
#pragma unroll
                for (int pr = 0; pr < 2; pr++) {
                    uint32_t r4[4];
                    ldsm_x4(bhHiB + pr * 16 * BSTH + j * 32, r4);
                    bh[pr * 2][0] = r4[0]; bh[pr * 2][1] = r4[1];
                    bh[pr * 2 + 1][0] = r4[2]; bh[pr * 2 + 1][1] = r4[3];
                    ldsm_x4(bhLoB + pr * 16 * BSTH + j * 32, r4);
                    bl[pr * 2][0] = r4[0]; bl[pr * 2][1] = r4[1];
                    bl[pr * 2 + 1][0] = r4[2]; bl[pr * 2 + 1][1] = r4[3];
                }
#pragma unroll
                for (int im = 0; im < 2; im++) {
                    uint32_t ah[4];
                    ldsm_x4(aHiB + 192 + im * 16 * AST + j * 32, ah);
#pragma unroll
                    for (int in = 0; in < 4; in++) {
                        mma16816(acc[im][in], ah, bh[in]);
                        mma16816(acc[im][in], ah, bl[in]);
                    }
                }
            }
        }

        __syncthreads();     // B + A readers done -> safe to restage

        // pipeline: next gate's B in flight; next step's w_in A staged
        if (s + 1 < 4 * TT) issue_cp(s + 1, smem_base, tid);
        if (q == 3 && t + 1 < TT) stage_win(out_w, smem_c, b0, t + 1, tid);

        // ---- elementwise on gate q (overlaps cp flight) ----
#pragma unroll
        for (int im = 0; im < 2; im++) {
#pragma unroll
            for (int in = 0; in < 4; in++) {
#pragma unroll
                for (int rh = 0; rh < 2; rh++) {
                    const int m = mw * 32 + im * 16 + (lane >> 2) + rh * 8;
                    const int n0 = nw * 32 + in * 8 + (lane & 3) * 2;
                    float g0 = acc[im][in][rh * 2]     + bias_s[q * HH + n0];
                    float g1 = acc[im][in][rh * 2 + 1] + bias_s[q * HH + n0 + 1];
                    if (q == 0) {
                        tmp[im][in][rh * 2]     = sig_fast(g0);
                        tmp[im][in][rh * 2 + 1] = sig_fast(g1);
                    } else if (q == 2) {
                        tmp[im][in][rh * 2]     *= tanh_fast(g0);
                        tmp[im][in][rh * 2 + 1] *= tanh_fast(g1);
                    } else if (q == 1) {
                        c_r[im][in][rh * 2] =
                            sig_fast(g0) * c_r[im][in][rh * 2] + tmp[im][in][rh * 2];
                        c_r[im][in][rh * 2 + 1] =
                            sig_fast(g1) * c_r[im][in][rh * 2 + 1] + tmp[im][in][rh * 2 + 1];
                    } else {
                        float h0 = sig_fast(g0) * tanh_fast(c_r[im][in][rh * 2]);
                        float h1 = sig_fast(g1) * tanh_fast(c_r[im][in][rh * 2 + 1]);
                        *(float2*)(out_enc + (((size_t)(b0 + m)) * TT + t) * HH + n0) =
                            make_float2(h0, h1);
                        if (t + 1 < TT)
                            *(uint32_t*)(smem_c + SM_A_HI + m * AST + (KW + n0) * 2) =
                                pack_bf16x2(h0, h1);
                    }
                }
            }
        }
    }
}

// ---------------------------------------------------------------------------
extern "C" void kernel_launch(void* const* d_in, const int* in_sizes, int n_in,
                              void* d_out, int out_size) {
    const float* x      = (const float*)d_in[0];
    const float* W_attn = (const float*)d_in[1];
    // d_in[2] = b_attn: cancels in softmax, unused
    const float* W_ih   = (const float*)d_in[3];
    const float* W_hh   = (const float*)d_in[4];
    const float* b_ih   = (const float*)d_in[5];
    const float* b_hh   = (const float*)d_in[6];

    float* out     = (float*)d_out;
    float* out_w   = out;                           // (B, 9, 81)
    float* out_enc = out + (size_t)NB * TT * DD;    // (B, 9, 128)

    prep_kernel<<<448, 256>>>(W_ih, W_hh, b_ih, b_hh);
    attn_kernel<<<NB / 8, 256>>>(x, W_attn, out_w);

    cudaFuncSetAttribute(rnn_tc_kernel, cudaFuncAttributeMaxDynamicSharedMemorySize, SM_TOTAL);
    rnn_tc_kernel<<<NB / BM, NTH, SM_TOTAL>>>(out_w, out_enc);
}

// round 16
// speedup vs baseline: 2.0599x; 1.0149x over previous
#include <cuda_runtime.h>
#include <cuda_bf16.h>
#include <cstdint>
#include <math.h>

// Problem constants
#define NB 32768   // batch
#define TT 9       // time steps (T-1)
#define DD 81      // input dim
#define HH 128     // hidden
#define NG 512     // 4*HH gates
#define KW 96      // w_in K padded (81 -> 96)
#define KT 224     // weight k-cols (96 w_in + 128 h)

// Tiling: BM=128 rows/CTA (256 CTAs), 512 threads = 16 warps (4m x 4n)
#define BM 128
#define NTH 512
#define AST 464    // A row stride bytes (224 bf16; 464%128=80 -> conflict-free)
#define BSTW 208   // B w_in region stride (96 bf16 used; 208%128=80 -> ok)
#define BSTH 272   // B h region stride (128 bf16 used; 272%128=16 -> ok)

// SMEM map (bytes) — 225792 total (fits 227KB cap)
#define SM_BIAS  0         // 2048
#define SM_A_HI  2048      // 128*464 = 59392 (w_in cols 0..95 | h cols 96..223)
#define SM_BW_HI 61440     // 128*208 = 26624
#define SM_BW_LO 88064     // 26624
#define SM_BH_HI 114688    // 128*272 = 34816
#define SM_BH_LO 149504    // 34816
#define SM_ATT   184320    // 128*81*4 = 41472 (attention weights, fp32)
#define SM_TOTAL 225792

// device scratch: weights pre-split bf16 hi/lo, row-major [n][224]
__device__ __align__(16) __nv_bfloat16 g_Bh[NG * KT];
__device__ __align__(16) __nv_bfloat16 g_Bl[NG * KT];
__device__ float g_bias[NG];

// ---------------------------------------------------------------------------
// prep: split weights into bf16 hi/lo, layout [n][k=224]; fuse biases.
// ---------------------------------------------------------------------------
__global__ void prep_kernel(const float* __restrict__ W_ih,
                            const float* __restrict__ W_hh,
                            const float* __restrict__ b_ih,
                            const float* __restrict__ b_hh) {
    int idx = blockIdx.x * blockDim.x + threadIdx.x;   // 512*224 = 114688
    if (idx < NG * KT) {
        int n = idx / KT;
        int k = idx - n * KT;
        float w = 0.f;
        if (k < DD) w = W_ih[n * DD + k];
        else if (k >= KW) w = W_hh[n * HH + (k - KW)];
        __nv_bfloat16 hi = __float2bfloat16(w);
        g_Bh[idx] = hi;
        g_Bl[idx] = __float2bfloat16(w - __bfloat162float(hi));
    }
    if (idx < NG) g_bias[idx] = b_ih[idx] + b_hh[idx];
}

// ---------------------------------------------------------------------------
// helpers
// ---------------------------------------------------------------------------
__device__ __forceinline__ uint32_t smem_u32(const void* p) {
    uint32_t a;
    asm("{ .reg .u64 t; cvta.to.shared.u64 t, %1; cvt.u32.u64 %0, t; }" : "=r"(a) : "l"(p));
    return a;
}
__device__ __forceinline__ void ldsm_x4(uint32_t addr, uint32_t* r) {
    asm volatile("ldmatrix.sync.aligned.m8n8.x4.shared.b16 {%0,%1,%2,%3}, [%4];"
                 : "=r"(r[0]), "=r"(r[1]), "=r"(r[2]), "=r"(r[3]) : "r"(addr));
}
__device__ __forceinline__ void mma16816(float* d, const uint32_t* a, const uint32_t* b) {
    asm volatile(
        "mma.sync.aligned.m16n8k16.row.col.f32.bf16.bf16.f32 "
        "{%0,%1,%2,%3}, {%4,%5,%6,%7}, {%8,%9}, {%0,%1,%2,%3};"
        : "+f"(d[0]), "+f"(d[1]), "+f"(d[2]), "+f"(d[3])
        : "r"(a[0]), "r"(a[1]), "r"(a[2]), "r"(a[3]), "r"(b[0]), "r"(b[1]));
}
__device__ __forceinline__ void cp16(uint32_t dst, const void* src) {
    asm volatile("cp.async.cg.shared.global [%0], [%1], 16;"
                 :: "r"(dst), "l"(__cvta_generic_to_global(src)) : "memory");
}
__device__ __forceinline__ void cp_commit() {
    asm volatile("cp.async.commit_group;" ::: "memory");
}
__device__ __forceinline__ void cp_waitall() {
    asm volatile("cp.async.wait_group 0;" ::: "memory");
}
__device__ __forceinline__ float tanh_fast(float x) {
    float y;
    asm("tanh.approx.f32 %0, %1;" : "=f"(y) : "f"(x));
    return y;
}
__device__ __forceinline__ float sig_fast(float x) {
    return fmaf(0.5f, tanh_fast(0.5f * x), 0.5f);
}
__device__ __forceinline__ uint32_t pack_bf16x2(float v0, float v1) {
    __nv_bfloat162 H(__float2bfloat16(v0), __float2bfloat16(v1));
    return *reinterpret_cast<uint32_t*>(&H);
}
// gate order i(0) -> g(2) -> f(1) -> o(3)
__device__ __forceinline__ int gate_of(int cc) {
    return (cc == 0) ? 0 : (cc == 1) ? 2 : (cc == 2) ? 1 : 3;
}

// issue cp.async for stream item s (s = t*4 + cc): w_in part + (t>0) h part
__device__ __forceinline__ void issue_cp(int s, uint32_t smem_base, int tid) {
    const int q = gate_of(s & 3);
#pragma unroll
    for (int it = 0; it < 3; it++) {           // w_in: 128*12 = 1536 16B-chunks
        int i = it * NTH + tid;
        int n = i / 12, ck = i - n * 12;
        size_t sb = ((size_t)(q * HH + n) * KT) * 2 + ck * 16;
        cp16(smem_base + SM_BW_HI + n * BSTW + ck * 16, (const char*)g_Bh + sb);
        cp16(smem_base + SM_BW_LO + n * BSTW + ck * 16, (const char*)g_Bl + sb);
    }
    if (s >= 4) {                              // h part needed only for t>0
#pragma unroll
        for (int it = 0; it < 4; it++) {       // h: 128*16 = 2048
            int i = it * NTH + tid;
            int n = i >> 4, ck = i & 15;
            size_t sb = ((size_t)(q * HH + n) * KT + KW) * 2 + ck * 16;
            cp16(smem_base + SM_BH_HI + n * BSTH + ck * 16, (const char*)g_Bh + sb);
            cp16(smem_base + SM_BH_LO + n * BSTH + ck * 16, (const char*)g_Bl + sb);
        }
    }
    cp_commit();
}

// stage w_in A tile for step t: w_in = att * x (att from smem), also write
// input_weighted to gmem. bf16 hi only (2-term split).
__device__ __forceinline__ void stage_win(const float* __restrict__ x,
                                          float* __restrict__ out_w,
                                          char* smem_c, int b0, int t, int tid) {
    const float* att_s = (const float*)(smem_c + SM_ATT);
    for (int p = tid; p < BM * 41; p += NTH) {
        int m = p / 41;
        int d = (p - m * 41) * 2;
        const float* src = x + (((size_t)(b0 + m)) * TT + t) * DD + d;
        float* dst = out_w + (((size_t)(b0 + m)) * TT + t) * DD + d;
        float v0 = att_s[m * DD + d] * src[0];
        float v1 = 0.f;
        dst[0] = v0;
        if (d + 1 < DD) {
            v1 = att_s[m * DD + d + 1] * src[1];
            dst[1] = v1;
        }
        *(uint32_t*)(smem_c + SM_A_HI + m * AST + d * 2) = pack_bf16x2(v0, v1);
    }
}

// ---------------------------------------------------------------------------
// fused attention + recurrent HMMA kernel: 1 CTA = 128 rows, 512 threads
// ---------------------------------------------------------------------------
__global__ __launch_bounds__(NTH, 1)
void rnn_tc_kernel(const float* __restrict__ x,
                   const float* __restrict__ W_attn,
                   float* __restrict__ out_w,
                   float* __restrict__ out_enc) {
    extern __shared__ char smem_c[];
    const uint32_t smem_base = smem_u32(smem_c);
    const int tid = threadIdx.x;
    const int wid = tid >> 5;
    const int lane = tid & 31;
    const int mw = wid & 3;        // 4 m-warps (rows 32*mw..)
    const int nw = wid >> 2;       // 4 n-warps (cols 32*nw..)
    const int b0 = blockIdx.x * BM;

    float* bias_s = (float*)(smem_c + SM_BIAS);
    float* att_s  = (float*)(smem_c + SM_ATT);
    for (int i = tid; i < NG; i += NTH) bias_s[i] = g_bias[i];
    {   // zero A_HI: 59392/16 = 3712 uint4
        uint4 z = make_uint4(0, 0, 0, 0);
        uint4* a4 = (uint4*)(smem_c + SM_A_HI);
        for (int i = tid; i < 3712; i += NTH) a4[i] = z;
    }

    // ---- fused attention: a[m][d] = softmax_d(sum_t x[m,t,d]*Wx[t]) ----
    {
        float wx[TT];
#pragma unroll
        for (int tt = 0; tt < TT; tt++) wx[tt] = W_attn[2 * HH + tt];
#pragma unroll 1
        for (int rr = 0; rr < BM / 16; rr++) {     // 8 iterations, 16 warps
            const int m = rr * 16 + wid;
            const float* xb = x + (size_t)(b0 + m) * TT * DD;
            float pre[3];
#pragma unroll
            for (int ii = 0; ii < 3; ii++) {
                int d = lane + 32 * ii;
                float p = 0.f;
#pragma unroll
                for (int tt = 0; tt < TT; tt++) {
                    float v = (d < DD) ? xb[tt * DD + d] : 0.f;
                    p = fmaf(v, wx[tt], p);
                }
                pre[ii] = (d < DD) ? p : -3.0e38f;
            }
            float mx = fmaxf(pre[0], fmaxf(pre[1], pre[2]));
#pragma unroll
            for (int o = 16; o > 0; o >>= 1)
                mx = fmaxf(mx, __shfl_xor_sync(0xffffffffu, mx, o));
            float ev[3];
            float sum = 0.f;
#pragma unroll
            for (int ii = 0; ii < 3; ii++) {
                int d = lane + 32 * ii;
                ev[ii] = (d < DD) ? __expf(pre[ii] - mx) : 0.f;
                sum += ev[ii];
            }
#pragma unroll
            for (int o = 16; o > 0; o >>= 1)
                sum += __shfl_xor_sync(0xffffffffu, sum, o);
            float inv = 1.f / sum;
#pragma unroll
            for (int ii = 0; ii < 3; ii++) {
                int d = lane + 32 * ii;
                if (d < DD) att_s[m * DD + d] = ev[ii] * inv;
            }
        }
    }
    __syncthreads();   // att_s + zeroed A visible

    // lane-resolved ldmatrix bases
    const uint32_t aHiB = smem_base + SM_A_HI + (mw * 32 + (lane & 15)) * AST
                        + ((lane >> 4) & 1) * 16;
    const int brow = (lane & 7) + ((lane >> 4) & 1) * 8;
    const int bcol = ((lane >> 3) & 1) * 16;
    const uint32_t bwHiB = smem_base + SM_BW_HI + (nw * 32 + brow) * BSTW + bcol;
    const uint32_t bwLoB = bwHiB + (SM_BW_LO - SM_BW_HI);
    const uint32_t bhHiB = smem_base + SM_BH_HI + (nw * 32 + brow) * BSTH + bcol;
    const uint32_t bhLoB = bhHiB + (SM_BH_LO - SM_BH_HI);

    float c_r[2][4][4];
    float tmp[2][4][4];
#pragma unroll
    for (int im = 0; im < 2; im++)
#pragma unroll
        for (int in = 0; in < 4; in++)
#pragma unroll
            for (int r = 0; r < 4; r++) c_r[im][in][r] = 0.f;

    // prologue: first gate's B in flight; w_in A for t=0
    issue_cp(0, smem_base, tid);
    stage_win(x, out_w, smem_c, b0, 0, tid);

#pragma unroll 1
    for (int s = 0; s < 4 * TT; s++) {
        const int t = s >> 2;
        const int q = gate_of(s & 3);

        cp_waitall();
        __syncthreads();     // B ready; A writes (w_in / h) visible to all

        // ---- GEMMs: w_in (k 0..95) then h (k 96..223), both 2-term ----
        float acc[2][4][4];
#pragma unroll
        for (int im = 0; im < 2; im++)
#pragma unroll
            for (int in = 0; in < 4; in++)
#pragma unroll
                for (int r = 0; r < 4; r++) acc[im][in][r] = 0.f;

#pragma unroll 1
        for (int j = 0; j < KW / 16; j++) {
            uint32_t bh[4][2], bl[4][2];
#pragma unroll
            for (int pr = 0; pr < 2; pr++) {
                uint32_t r4[4];
                ldsm_x4(bwHiB + pr * 16 * BSTW + j * 32, r4);
                bh[pr * 2][0] = r4[0]; bh[pr * 2][1] = r4[1];
                bh[pr * 2 + 1][0] = r4[2]; bh[pr * 2 + 1][1] = r4[3];
                ldsm_x4(bwLoB + pr * 16 * BSTW + j * 32, r4);
                bl[pr * 2][0] = r4[0]; bl[pr * 2][1] = r4[1];
                bl[pr * 2 + 1][0] = r4[2]; bl[pr * 2 + 1][1] = r4[3];
            }
#pragma unroll
            for (int im = 0; im < 2; im++) {
                uint32_t ah[4];
                ldsm_x4(aHiB + im * 16 * AST + j * 32, ah);
#pragma unroll
                for (int in = 0; in < 4; in++) {
                    mma16816(acc[im][in], ah, bh[in]);
                    mma16816(acc[im][in], ah, bl[in]);
                }
            }
        }
        if (t > 0) {
#pragma unroll 1
            for (int j = 0; j < HH / 16; j++) {
                uint32_t bh[4][2], bl[4][2];
#pragma unroll
                for (int pr = 0; pr < 2; pr++) {
                    uint32_t r4[4];
                    ldsm_x4(bhHiB + pr * 16 * BSTH + j * 32, r4);
                    bh[pr * 2][0] = r4[0]; bh[pr * 2][1] = r4[1];
                    bh[pr * 2 + 1][0] = r4[2]; bh[pr * 2 + 1][1] = r4[3];
                    ldsm_x4(bhLoB + pr * 16 * BSTH + j * 32, r4);
                    bl[pr * 2][0] = r4[0]; bl[pr * 2][1] = r4[1];
                    bl[pr * 2 + 1][0] = r4[2]; bl[pr * 2 + 1][1] = r4[3];
                }
#pragma unroll
                for (int im = 0; im < 2; im++) {
                    uint32_t ah[4];
                    ldsm_x4(aHiB + 192 + im * 16 * AST + j * 32, ah);
#pragma unroll
                    for (int in = 0; in < 4; in++) {
                        mma16816(acc[im][in], ah, bh[in]);
                        mma16816(acc[im][in], ah, bl[in]);
                    }
                }
            }
        }

        __syncthreads();     // B + A readers done -> safe to restage

        // pipeline: next gate's B in flight; next step's w_in A staged
        if (s + 1 < 4 * TT) issue_cp(s + 1, smem_base, tid);
        if (q == 3 && t + 1 < TT) stage_win(x, out_w, smem_c, b0, t + 1, tid);

        // ---- elementwise on gate q (overlaps cp flight) ----
#pragma unroll
        for (int im = 0; im < 2; im++) {
#pragma unroll
            for (int in = 0; in < 4; in++) {
#pragma unroll
                for (int rh = 0; rh < 2; rh++) {
                    const int m = mw * 32 + im * 16 + (lane >> 2) + rh * 8;
                    const int n0 = nw * 32 + in * 8 + (lane & 3) * 2;
                    float g0 = acc[im][in][rh * 2]     + bias_s[q * HH + n0];
                    float g1 = acc[im][in][rh * 2 + 1] + bias_s[q * HH + n0 + 1];
                    if (q == 0) {
                        tmp[im][in][rh * 2]     = sig_fast(g0);
                        tmp[im][in][rh * 2 + 1] = sig_fast(g1);
                    } else if (q == 2) {
                        tmp[im][in][rh * 2]     *= tanh_fast(g0);
                        tmp[im][in][rh * 2 + 1] *= tanh_fast(g1);
                    } else if (q == 1) {
                        c_r[im][in][rh * 2] =
                            sig_fast(g0) * c_r[im][in][rh * 2] + tmp[im][in][rh * 2];
                        c_r[im][in][rh * 2 + 1] =
                            sig_fast(g1) * c_r[im][in][rh * 2 + 1] + tmp[im][in][rh * 2 + 1];
                    } else {
                        float h0 = sig_fast(g0) * tanh_fast(c_r[im][in][rh * 2]);
                        float h1 = sig_fast(g1) * tanh_fast(c_r[im][in][rh * 2 + 1]);
                        *(float2*)(out_enc + (((size_t)(b0 + m)) * TT + t) * HH + n0) =
                            make_float2(h0, h1);
                        if (t + 1 < TT)
                            *(uint32_t*)(smem_c + SM_A_HI + m * AST + (KW + n0) * 2) =
                                pack_bf16x2(h0, h1);
                    }
                }
            }
        }
    }
}

// ---------------------------------------------------------------------------
extern "C" void kernel_launch(void* const* d_in, const int* in_sizes, int n_in,
                              void* d_out, int out_size) {
    const float* x      = (const float*)d_in[0];
    const float* W_attn = (const float*)d_in[1];
    // d_in[2] = b_attn: cancels in softmax, unused
    const float* W_ih   = (const float*)d_in[3];
    const float* W_hh   = (const float*)d_in[4];
    const float* b_ih   = (const float*)d_in[5];
    const float* b_hh   = (const float*)d_in[6];

    float* out     = (float*)d_out;
    float* out_w   = out;                           // (B, 9, 81)
    float* out_enc = out + (size_t)NB * TT * DD;    // (B, 9, 128)

    prep_kernel<<<448, 256>>>(W_ih, W_hh, b_ih, b_hh);

    cudaFuncSetAttribute(rnn_tc_kernel, cudaFuncAttributeMaxDynamicSharedMemorySize, SM_TOTAL);
    rnn_tc_kernel<<<NB / BM, NTH, SM_TOTAL>>>(x, W_attn, out_w, out_enc);
}